// round 4
// baseline (speedup 1.0000x reference)
#include <cuda_runtime.h>

#define N_NODES 100000
#define N_EDGES 1600000
#define IN_DIM  128
#define HID_DIM 64
#define OUT_DIM 32

// ---- device scratch (static globals: no runtime allocation allowed) ----
__device__ int   g_deg[N_NODES];
__device__ int   g_off[N_NODES + 1];
__device__ int   g_fill[N_NODES];
__device__ int   g_csr[N_EDGES];
__device__ float g_dinv[N_NODES];
__device__ float g_h1[N_NODES * HID_DIM];   // x @ W1
__device__ float g_a1[N_NODES * HID_DIM];   // relu(agg(h1) + b1)
__device__ float g_h2[N_NODES * OUT_DIM];   // a1 @ W2

// device-side buffer selector (host never touches device symbols)
__device__ __forceinline__ float* buf_sel(int sel) {
    switch (sel) {
        case 0: return g_h1;
        case 1: return g_a1;
        default: return g_h2;
    }
}

// ---------------------------------------------------------------- degree
__global__ void zero_deg_kernel() {
    int i = blockIdx.x * blockDim.x + threadIdx.x;
    if (i < N_NODES) g_deg[i] = 0;
}

// edge_index is int32 (JAX default x64-disabled downcasts int64 -> int32)
__global__ void count_kernel(const int* __restrict__ ei) {
    int e = blockIdx.x * blockDim.x + threadIdx.x;
    if (e < N_EDGES) {
        unsigned d = (unsigned)ei[N_EDGES + e];
        if (d < N_NODES) atomicAdd(&g_deg[d], 1);
    }
}

// single-block exclusive scan over 100k degrees; also computes dinv
__global__ void scan_kernel() {
    __shared__ int s[1024];
    const int t = threadIdx.x;
    const int chunk = (N_NODES + 1023) / 1024;   // 98
    const int base = t * chunk;

    int sum = 0;
    for (int i = 0; i < chunk; i++) {
        int idx = base + i;
        if (idx < N_NODES) sum += g_deg[idx];
    }
    s[t] = sum;
    __syncthreads();
    // Kogge-Stone inclusive scan
    for (int off = 1; off < 1024; off <<= 1) {
        int v = (t >= off) ? s[t - off] : 0;
        __syncthreads();
        s[t] += v;
        __syncthreads();
    }
    int run = (t == 0) ? 0 : s[t - 1];
    for (int i = 0; i < chunk; i++) {
        int idx = base + i;
        if (idx < N_NODES) {
            g_off[idx]  = run;
            g_fill[idx] = run;
            int d = g_deg[idx];
            run += d;
            g_dinv[idx] = rsqrtf((float)(d + 1));   // +1 self loop
        }
    }
    if (t == 1023) g_off[N_NODES] = N_EDGES;
}

__global__ void scatter_kernel(const int* __restrict__ ei) {
    int e = blockIdx.x * blockDim.x + threadIdx.x;
    if (e < N_EDGES) {
        unsigned src = (unsigned)ei[e];
        unsigned dst = (unsigned)ei[N_EDGES + e];
        if (src < N_NODES && dst < N_NODES) {
            int pos = atomicAdd(&g_fill[dst], 1);
            if (pos < N_EDGES) g_csr[pos] = (int)src;
        }
    }
}

// ---------------------------------------------------------------- GEMM
// H[N, FOUT] = X[N, FIN] @ W[FIN, FOUT]; W cached in SMEM,
// TR-row x 4-col register tiles, float4 loads throughout.
template <int FIN, int FOUT, int TR, int XSEL>
__global__ void gemm_kernel(const float* __restrict__ Xarg,
                            const float* __restrict__ W,
                            int out_sel) {
    constexpr int CG = FOUT / 4;      // col groups (float4 wide)
    constexpr int RG = 256 / CG;      // row groups per block
    constexpr int RB = RG * TR;       // rows per block

    const float* X = (XSEL < 0) ? Xarg : buf_sel(XSEL);
    float* H = buf_sel(out_sel);

    __shared__ float Ws[FIN * FOUT];
    for (int i = threadIdx.x; i < FIN * FOUT; i += 256) Ws[i] = W[i];
    __syncthreads();

    const int cg   = threadIdx.x % CG;
    const int rg   = threadIdx.x / CG;
    const int row0 = blockIdx.x * RB + rg * TR;

    float acc[TR][4];
#pragma unroll
    for (int r = 0; r < TR; r++)
#pragma unroll
        for (int c = 0; c < 4; c++) acc[r][c] = 0.f;

    const float4* X4 = (const float4*)X;

#pragma unroll
    for (int kk = 0; kk < FIN / 4; kk++) {
        float4 wv[4];
#pragma unroll
        for (int k = 0; k < 4; k++)
            wv[k] = *(const float4*)&Ws[(kk * 4 + k) * FOUT + cg * 4];
#pragma unroll
        for (int r = 0; r < TR; r++) {
            int row = row0 + r;
            if (row < N_NODES) {
                float4 xv = X4[row * (FIN / 4) + kk];
                float xk[4] = {xv.x, xv.y, xv.z, xv.w};
#pragma unroll
                for (int k = 0; k < 4; k++) {
                    acc[r][0] += xk[k] * wv[k].x;
                    acc[r][1] += xk[k] * wv[k].y;
                    acc[r][2] += xk[k] * wv[k].z;
                    acc[r][3] += xk[k] * wv[k].w;
                }
            }
        }
    }

#pragma unroll
    for (int r = 0; r < TR; r++) {
        int row = row0 + r;
        if (row < N_NODES) {
            float4 o = {acc[r][0], acc[r][1], acc[r][2], acc[r][3]};
            *(float4*)&H[row * FOUT + cg * 4] = o;
        }
    }
}

// ---------------------------------------------------------------- aggregate
// One warp per destination node: acc = dinv[i]^2 * h[i] + sum_j dinv_i*dinv_s*h[src]
// then + bias (and relu for layer 1). Atomic-free, coalesced output.
template <int F, bool RELU, int HSEL>
__global__ void agg_kernel(const float* __restrict__ bias,
                           float* __restrict__ Oarg,
                           int out_sel) {      // -1 => use Oarg
    const float* H = buf_sel(HSEL);
    float* O = (out_sel < 0) ? Oarg : buf_sel(out_sel);

    int node = (blockIdx.x * blockDim.x + threadIdx.x) >> 5;
    int lane = threadIdx.x & 31;
    if (node >= N_NODES) return;

    constexpr int FPL = F / 32;       // features per lane (2 or 1)
    float di = g_dinv[node];
    float acc[FPL];
#pragma unroll
    for (int p = 0; p < FPL; p++)
        acc[p] = di * di * H[node * F + p * 32 + lane];

    int beg = g_off[node];
    int end = g_off[node + 1];
    for (int j = beg; j < end; j++) {
        int s = g_csr[j];
        float w = di * g_dinv[s];
#pragma unroll
        for (int p = 0; p < FPL; p++)
            acc[p] += w * H[s * F + p * 32 + lane];
    }

#pragma unroll
    for (int p = 0; p < FPL; p++) {
        float v = acc[p] + bias[p * 32 + lane];
        if (RELU) v = fmaxf(v, 0.f);
        O[node * F + p * 32 + lane] = v;
    }
}

// ---------------------------------------------------------------- launch
extern "C" void kernel_launch(void* const* d_in, const int* in_sizes, int n_in,
                              void* d_out, int out_size) {
    const float* x  = (const float*)d_in[0];
    const int*   ei = (const int*)d_in[1];      // int32 edge_index [2, E]
    const float* W1 = (const float*)d_in[2];
    const float* b1 = (const float*)d_in[3];
    const float* W2 = (const float*)d_in[4];
    const float* b2 = (const float*)d_in[5];
    float*       out = (float*)d_out;

    // CSR build
    zero_deg_kernel<<<(N_NODES + 255) / 256, 256>>>();
    count_kernel<<<(N_EDGES + 255) / 256, 256>>>(ei);
    scan_kernel<<<1, 1024>>>();
    scatter_kernel<<<(N_EDGES + 255) / 256, 256>>>(ei);

    // layer 1: gemm x@W1 -> g_h1 ; agg g_h1 -> g_a1 (relu)
    gemm_kernel<IN_DIM, HID_DIM, 4, -1><<<(N_NODES + 63) / 64, 256>>>(x, W1, 0);
    agg_kernel<HID_DIM, true, 0><<<(N_NODES * 32 + 255) / 256, 256>>>(b1, nullptr, 1);

    // layer 2: gemm g_a1@W2 -> g_h2 ; agg g_h2 -> out
    gemm_kernel<HID_DIM, OUT_DIM, 4, 1><<<(N_NODES + 127) / 128, 256>>>(nullptr, W2, 2);
    agg_kernel<OUT_DIM, false, 2><<<(N_NODES * 32 + 255) / 256, 256>>>(b2, out, -1);
}

// round 6
// speedup vs baseline: 2.8181x; 2.8181x over previous
#include <cuda_runtime.h>

#define N_NODES 100000
#define N_EDGES 1600000
#define IN_DIM  128
#define HID_DIM 64
#define OUT_DIM 32

#define NB_SCAN ((N_NODES + 255) / 256)   // 391 scan blocks

// ---- device scratch (static globals: no runtime allocation allowed) ----
__device__ int   g_deg[N_NODES];
__device__ int   g_off[N_NODES + 1];
__device__ int   g_fill[N_NODES];
__device__ int   g_csr[N_EDGES];
__device__ int   g_part[NB_SCAN];          // per-block degree sums
__device__ int   g_poff[NB_SCAN];          // exclusive offsets of blocks
__device__ float g_dinv[N_NODES];
__device__ float g_h1[N_NODES * HID_DIM];  // x @ W1
__device__ float g_a1[N_NODES * HID_DIM];  // relu(agg(h1) + b1)
__device__ float g_h2[N_NODES * OUT_DIM];  // a1 @ W2

// device-side buffer selector (host never touches device symbols)
__device__ __forceinline__ float* buf_sel(int sel) {
    switch (sel) {
        case 0: return g_h1;
        case 1: return g_a1;
        default: return g_h2;
    }
}

// ---------------------------------------------------------------- CSR build
__global__ void zero_deg_kernel() {
    int i = blockIdx.x * blockDim.x + threadIdx.x;
    if (i < N_NODES) g_deg[i] = 0;
}

__global__ void count_kernel(const int* __restrict__ ei) {
    int e = blockIdx.x * blockDim.x + threadIdx.x;
    if (e < N_EDGES) {
        unsigned d = (unsigned)ei[N_EDGES + e];
        if (d < N_NODES) atomicAdd(&g_deg[d], 1);
    }
}

// stage 1: per-block reduction of degrees (391 blocks x 256 threads)
__global__ void scan_reduce_kernel() {
    __shared__ int s[256];
    int t = threadIdx.x;
    int idx = blockIdx.x * 256 + t;
    s[t] = (idx < N_NODES) ? g_deg[idx] : 0;
    __syncthreads();
#pragma unroll
    for (int off = 128; off > 0; off >>= 1) {
        if (t < off) s[t] += s[t + off];
        __syncthreads();
    }
    if (t == 0) g_part[blockIdx.x] = s[0];
}

// stage 2: single block scans the 391 partials (tiny, fast)
__global__ void scan_part_kernel() {
    __shared__ int s[512];
    int t = threadIdx.x;
    s[t] = (t < NB_SCAN) ? g_part[t] : 0;
    __syncthreads();
#pragma unroll
    for (int off = 1; off < 512; off <<= 1) {
        int v = (t >= off) ? s[t - off] : 0;
        __syncthreads();
        s[t] += v;
        __syncthreads();
    }
    if (t < NB_SCAN) g_poff[t] = (t == 0) ? 0 : s[t - 1];
    if (t == 0) g_off[N_NODES] = N_EDGES;
}

// stage 3: per-block exclusive scan + write offsets/fill/dinv
__global__ void scan_final_kernel() {
    __shared__ int s[256];
    int t = threadIdx.x;
    int idx = blockIdx.x * 256 + t;
    int d = (idx < N_NODES) ? g_deg[idx] : 0;
    s[t] = d;
    __syncthreads();
#pragma unroll
    for (int off = 1; off < 256; off <<= 1) {
        int v = (t >= off) ? s[t - off] : 0;
        __syncthreads();
        s[t] += v;
        __syncthreads();
    }
    if (idx < N_NODES) {
        int off = g_poff[blockIdx.x] + s[t] - d;   // exclusive
        g_off[idx]  = off;
        g_fill[idx] = off;
        g_dinv[idx] = rsqrtf((float)(d + 1));      // +1 self loop
    }
}

__global__ void scatter_kernel(const int* __restrict__ ei) {
    int e = blockIdx.x * blockDim.x + threadIdx.x;
    if (e < N_EDGES) {
        unsigned src = (unsigned)ei[e];
        unsigned dst = (unsigned)ei[N_EDGES + e];
        if (src < N_NODES && dst < N_NODES) {
            int pos = atomicAdd(&g_fill[dst], 1);
            if (pos < N_EDGES) g_csr[pos] = (int)src;
        }
    }
}

// ---------------------------------------------------------------- GEMM
// H[N, FOUT] = X[N, FIN] @ W[FIN, FOUT]; W in SMEM.
// TR rows x CPT cols per thread; row index clamped (stores guarded) so the
// inner loop has no branches.
template <int FIN, int FOUT, int TR, int CPT, int XSEL>
__launch_bounds__(256)
__global__ void gemm_kernel(const float* __restrict__ Xarg,
                            const float* __restrict__ W,
                            int out_sel) {
    constexpr int CG = FOUT / CPT;    // col groups per row
    constexpr int RG = 256 / CG;      // row groups per block
    constexpr int RB = RG * TR;       // rows per block
    constexpr int C4 = CPT / 4;       // float4s per thread-column-tile

    const float* X = (XSEL < 0) ? Xarg : buf_sel(XSEL);
    float* H = buf_sel(out_sel);

    __shared__ float Ws[FIN * FOUT];
    for (int i = threadIdx.x; i < FIN * FOUT; i += 256) Ws[i] = W[i];
    __syncthreads();

    const int cg   = threadIdx.x % CG;
    const int rg   = threadIdx.x / CG;
    const int row0 = blockIdx.x * RB + rg * TR;

    float acc[TR][CPT];
#pragma unroll
    for (int r = 0; r < TR; r++)
#pragma unroll
        for (int c = 0; c < CPT; c++) acc[r][c] = 0.f;

    const float4* X4 = (const float4*)X;
    int rowc[TR];
#pragma unroll
    for (int r = 0; r < TR; r++) {
        int row = row0 + r;
        rowc[r] = (row < N_NODES) ? row : (N_NODES - 1);   // clamp
    }

#pragma unroll
    for (int kk = 0; kk < FIN / 4; kk++) {
        float4 xv[TR];
#pragma unroll
        for (int r = 0; r < TR; r++)
            xv[r] = X4[rowc[r] * (FIN / 4) + kk];
#pragma unroll
        for (int k4 = 0; k4 < 4; k4++) {
            float4 wv[C4];
#pragma unroll
            for (int c = 0; c < C4; c++)
                wv[c] = *(const float4*)&Ws[(kk * 4 + k4) * FOUT + cg * CPT + c * 4];
#pragma unroll
            for (int r = 0; r < TR; r++) {
                float xk = (k4 == 0) ? xv[r].x : (k4 == 1) ? xv[r].y
                         : (k4 == 2) ? xv[r].z : xv[r].w;
#pragma unroll
                for (int c = 0; c < C4; c++) {
                    acc[r][c * 4 + 0] += xk * wv[c].x;
                    acc[r][c * 4 + 1] += xk * wv[c].y;
                    acc[r][c * 4 + 2] += xk * wv[c].z;
                    acc[r][c * 4 + 3] += xk * wv[c].w;
                }
            }
        }
    }

#pragma unroll
    for (int r = 0; r < TR; r++) {
        int row = row0 + r;
        if (row < N_NODES) {
#pragma unroll
            for (int c = 0; c < C4; c++) {
                float4 o = {acc[r][c * 4 + 0], acc[r][c * 4 + 1],
                            acc[r][c * 4 + 2], acc[r][c * 4 + 3]};
                *(float4*)&H[row * FOUT + cg * CPT + c * 4] = o;
            }
        }
    }
}

// ---------------------------------------------------------------- aggregate
// One warp per destination node, float2 lanes for F=64 (scalar for F=32),
// 2-edge unroll for memory-level parallelism. Atomic-free, coalesced output.
template <bool RELU, int HSEL>
__global__ void agg64_kernel(const float* __restrict__ bias,
                             float* __restrict__ Oarg, int out_sel) {
    const float2* H2 = (const float2*)buf_sel(HSEL);
    float2* O2 = (float2*)((out_sel < 0) ? Oarg : buf_sel(out_sel));

    int node = (blockIdx.x * blockDim.x + threadIdx.x) >> 5;
    int lane = threadIdx.x & 31;
    if (node >= N_NODES) return;

    float di = g_dinv[node];
    float2 h = H2[node * 32 + lane];
    float ax = di * di * h.x, ay = di * di * h.y;

    int beg = g_off[node];
    int end = g_off[node + 1];
    int j = beg;
    for (; j + 2 <= end; j += 2) {
        int s0 = g_csr[j], s1 = g_csr[j + 1];
        float w0 = di * g_dinv[s0];
        float w1 = di * g_dinv[s1];
        float2 v0 = H2[s0 * 32 + lane];
        float2 v1 = H2[s1 * 32 + lane];
        ax += w0 * v0.x + w1 * v1.x;
        ay += w0 * v0.y + w1 * v1.y;
    }
    if (j < end) {
        int s = g_csr[j];
        float w = di * g_dinv[s];
        float2 v = H2[s * 32 + lane];
        ax += w * v.x;
        ay += w * v.y;
    }

    float2 bb = ((const float2*)bias)[lane];
    ax += bb.x; ay += bb.y;
    if (RELU) { ax = fmaxf(ax, 0.f); ay = fmaxf(ay, 0.f); }
    float2 o = {ax, ay};
    O2[node * 32 + lane] = o;
}

template <bool RELU, int HSEL>
__global__ void agg32_kernel(const float* __restrict__ bias,
                             float* __restrict__ Oarg, int out_sel) {
    const float* H = buf_sel(HSEL);
    float* O = (out_sel < 0) ? Oarg : buf_sel(out_sel);

    int node = (blockIdx.x * blockDim.x + threadIdx.x) >> 5;
    int lane = threadIdx.x & 31;
    if (node >= N_NODES) return;

    float di = g_dinv[node];
    float acc = di * di * H[node * 32 + lane];

    int beg = g_off[node];
    int end = g_off[node + 1];
    int j = beg;
    for (; j + 2 <= end; j += 2) {
        int s0 = g_csr[j], s1 = g_csr[j + 1];
        float w0 = di * g_dinv[s0];
        float w1 = di * g_dinv[s1];
        acc += w0 * H[s0 * 32 + lane] + w1 * H[s1 * 32 + lane];
    }
    if (j < end) {
        int s = g_csr[j];
        acc += di * g_dinv[s] * H[s * 32 + lane];
    }

    float v = acc + bias[lane];
    if (RELU) v = fmaxf(v, 0.f);
    O[node * 32 + lane] = v;
}

// ---------------------------------------------------------------- launch
extern "C" void kernel_launch(void* const* d_in, const int* in_sizes, int n_in,
                              void* d_out, int out_size) {
    const float* x  = (const float*)d_in[0];
    const int*   ei = (const int*)d_in[1];      // int32 edge_index [2, E]
    const float* W1 = (const float*)d_in[2];
    const float* b1 = (const float*)d_in[3];
    const float* W2 = (const float*)d_in[4];
    const float* b2 = (const float*)d_in[5];
    float*       out = (float*)d_out;

    // CSR build (parallel hierarchical scan)
    zero_deg_kernel<<<(N_NODES + 255) / 256, 256>>>();
    count_kernel<<<(N_EDGES + 255) / 256, 256>>>(ei);
    scan_reduce_kernel<<<NB_SCAN, 256>>>();
    scan_part_kernel<<<1, 512>>>();
    scan_final_kernel<<<NB_SCAN, 256>>>();
    scatter_kernel<<<(N_EDGES + 255) / 256, 256>>>(ei);

    // layer 1: gemm x@W1 -> g_h1 ; agg g_h1 -> g_a1 (relu)
    gemm_kernel<IN_DIM, HID_DIM, 4, 16, -1>
        <<<(N_NODES + 255) / 256, 256>>>(x, W1, 0);
    agg64_kernel<true, 0><<<(N_NODES * 32 + 255) / 256, 256>>>(b1, nullptr, 1);

    // layer 2: gemm g_a1@W2 -> g_h2 ; agg g_h2 -> out
    gemm_kernel<HID_DIM, OUT_DIM, 4, 16, 1>
        <<<(N_NODES + 511) / 512, 256>>>(nullptr, W2, 2);
    agg32_kernel<false, 2><<<(N_NODES * 32 + 255) / 256, 256>>>(b2, out, -1);
}

// round 9
// speedup vs baseline: 3.0909x; 1.0968x over previous
#include <cuda_runtime.h>

#define N_NODES 100000
#define N_EDGES 1600000
#define IN_DIM  128
#define HID_DIM 64
#define OUT_DIM 32

#define NB_SCAN ((N_NODES + 255) / 256)   // 391 scan blocks

// ---- device scratch (static globals: no runtime allocation allowed) ----
__device__ int   g_deg[N_NODES];
__device__ int   g_off[N_NODES + 1];
__device__ int   g_fill[N_NODES];
__device__ int   g_csr[N_EDGES];
__device__ int   g_part[NB_SCAN];
__device__ int   g_poff[NB_SCAN];
__device__ float g_dinv[N_NODES];
__device__ float g_h1[N_NODES * HID_DIM];  // x @ W1
__device__ float g_a1[N_NODES * HID_DIM];  // relu(agg(h1) + b1)
__device__ float g_h2[N_NODES * OUT_DIM];  // a1 @ W2

__device__ __forceinline__ float* buf_sel(int sel) {
    switch (sel) {
        case 0: return g_h1;
        case 1: return g_a1;
        default: return g_h2;
    }
}

// ---------------------------------------------------------------- CSR build
__global__ void zero_deg_kernel() {
    int i = blockIdx.x * blockDim.x + threadIdx.x;
    if (i * 4 < N_NODES) {
        int4 z = {0, 0, 0, 0};
        if (i * 4 + 3 < N_NODES) *(int4*)&g_deg[i * 4] = z;
        else for (int k = i * 4; k < N_NODES; k++) g_deg[k] = 0;
    }
}

// 4 edges per thread via int4 loads (dst half of edge_index)
__global__ void count_kernel(const int* __restrict__ ei) {
    int t = blockIdx.x * blockDim.x + threadIdx.x;
    int e = t * 4;
    if (e + 4 <= N_EDGES) {
        int4 d4 = *(const int4*)&ei[N_EDGES + e];
        if ((unsigned)d4.x < N_NODES) atomicAdd(&g_deg[d4.x], 1);
        if ((unsigned)d4.y < N_NODES) atomicAdd(&g_deg[d4.y], 1);
        if ((unsigned)d4.z < N_NODES) atomicAdd(&g_deg[d4.z], 1);
        if ((unsigned)d4.w < N_NODES) atomicAdd(&g_deg[d4.w], 1);
    } else {
        for (int k = e; k < N_EDGES; k++) {
            unsigned d = (unsigned)ei[N_EDGES + k];
            if (d < N_NODES) atomicAdd(&g_deg[d], 1);
        }
    }
}

__global__ void scan_reduce_kernel() {
    __shared__ int s[256];
    int t = threadIdx.x;
    int idx = blockIdx.x * 256 + t;
    s[t] = (idx < N_NODES) ? g_deg[idx] : 0;
    __syncthreads();
#pragma unroll
    for (int off = 128; off > 0; off >>= 1) {
        if (t < off) s[t] += s[t + off];
        __syncthreads();
    }
    if (t == 0) g_part[blockIdx.x] = s[0];
}

__global__ void scan_part_kernel() {
    __shared__ int s[512];
    int t = threadIdx.x;
    s[t] = (t < NB_SCAN) ? g_part[t] : 0;
    __syncthreads();
#pragma unroll
    for (int off = 1; off < 512; off <<= 1) {
        int v = (t >= off) ? s[t - off] : 0;
        __syncthreads();
        s[t] += v;
        __syncthreads();
    }
    if (t < NB_SCAN) g_poff[t] = (t == 0) ? 0 : s[t - 1];
    if (t == 0) g_off[N_NODES] = N_EDGES;
}

__global__ void scan_final_kernel() {
    __shared__ int s[256];
    int t = threadIdx.x;
    int idx = blockIdx.x * 256 + t;
    int d = (idx < N_NODES) ? g_deg[idx] : 0;
    s[t] = d;
    __syncthreads();
#pragma unroll
    for (int off = 1; off < 256; off <<= 1) {
        int v = (t >= off) ? s[t - off] : 0;
        __syncthreads();
        s[t] += v;
        __syncthreads();
    }
    if (idx < N_NODES) {
        int off = g_poff[blockIdx.x] + s[t] - d;
        g_off[idx]  = off;
        g_fill[idx] = off;
        g_dinv[idx] = rsqrtf((float)(d + 1));
    }
}

// 2 edges per thread via int2 loads on src and dst halves
__global__ void scatter_kernel(const int* __restrict__ ei) {
    int t = blockIdx.x * blockDim.x + threadIdx.x;
    int e = t * 2;
    if (e + 2 <= N_EDGES) {
        int2 s2 = *(const int2*)&ei[e];
        int2 d2 = *(const int2*)&ei[N_EDGES + e];
        if ((unsigned)s2.x < N_NODES && (unsigned)d2.x < N_NODES)
            g_csr[atomicAdd(&g_fill[d2.x], 1)] = s2.x;
        if ((unsigned)s2.y < N_NODES && (unsigned)d2.y < N_NODES)
            g_csr[atomicAdd(&g_fill[d2.y], 1)] = s2.y;
    } else if (e < N_EDGES) {
        unsigned src = (unsigned)ei[e];
        unsigned dst = (unsigned)ei[N_EDGES + e];
        if (src < N_NODES && dst < N_NODES)
            g_csr[atomicAdd(&g_fill[dst], 1)] = (int)src;
    }
}

// ---------------------------------------------------------------- GEMM
template <int FIN, int FOUT, int TR, int CPT, int XSEL>
__launch_bounds__(256)
__global__ void gemm_kernel(const float* __restrict__ Xarg,
                            const float* __restrict__ W,
                            int out_sel) {
    constexpr int CG = FOUT / CPT;
    constexpr int RG = 256 / CG;
    constexpr int RB = RG * TR;
    constexpr int C4 = CPT / 4;

    const float* X = (XSEL < 0) ? Xarg : buf_sel(XSEL);
    float* H = buf_sel(out_sel);

    __shared__ float Ws[FIN * FOUT];
    for (int i = threadIdx.x; i < FIN * FOUT; i += 256) Ws[i] = W[i];
    __syncthreads();

    const int cg   = threadIdx.x % CG;
    const int rg   = threadIdx.x / CG;
    const int row0 = blockIdx.x * RB + rg * TR;

    float acc[TR][CPT];
#pragma unroll
    for (int r = 0; r < TR; r++)
#pragma unroll
        for (int c = 0; c < CPT; c++) acc[r][c] = 0.f;

    const float4* X4 = (const float4*)X;
    int rowc[TR];
#pragma unroll
    for (int r = 0; r < TR; r++) {
        int row = row0 + r;
        rowc[r] = (row < N_NODES) ? row : (N_NODES - 1);
    }

#pragma unroll
    for (int kk = 0; kk < FIN / 4; kk++) {
        float4 xv[TR];
#pragma unroll
        for (int r = 0; r < TR; r++)
            xv[r] = X4[rowc[r] * (FIN / 4) + kk];
#pragma unroll
        for (int k4 = 0; k4 < 4; k4++) {
            float4 wv[C4];
#pragma unroll
            for (int c = 0; c < C4; c++)
                wv[c] = *(const float4*)&Ws[(kk * 4 + k4) * FOUT + cg * CPT + c * 4];
#pragma unroll
            for (int r = 0; r < TR; r++) {
                float xk = (k4 == 0) ? xv[r].x : (k4 == 1) ? xv[r].y
                         : (k4 == 2) ? xv[r].z : xv[r].w;
#pragma unroll
                for (int c = 0; c < C4; c++) {
                    acc[r][c * 4 + 0] += xk * wv[c].x;
                    acc[r][c * 4 + 1] += xk * wv[c].y;
                    acc[r][c * 4 + 2] += xk * wv[c].z;
                    acc[r][c * 4 + 3] += xk * wv[c].w;
                }
            }
        }
    }

#pragma unroll
    for (int r = 0; r < TR; r++) {
        int row = row0 + r;
        if (row < N_NODES) {
#pragma unroll
            for (int c = 0; c < C4; c++) {
                float4 o = {acc[r][c * 4 + 0], acc[r][c * 4 + 1],
                            acc[r][c * 4 + 2], acc[r][c * 4 + 3]};
                *(float4*)&H[row * FOUT + cg * CPT + c * 4] = o;
            }
        }
    }
}

// ---------------------------------------------------------------- aggregate
// warp per node; float2 lanes (F=64) / scalar (F=32); 4-edge unroll for MLP.
template <bool RELU, int HSEL>
__global__ void agg64_kernel(const float* __restrict__ bias,
                             float* __restrict__ Oarg, int out_sel) {
    const float2* H2 = (const float2*)buf_sel(HSEL);
    float2* O2 = (float2*)((out_sel < 0) ? Oarg : buf_sel(out_sel));

    int node = (blockIdx.x * blockDim.x + threadIdx.x) >> 5;
    int lane = threadIdx.x & 31;
    if (node >= N_NODES) return;

    float di = g_dinv[node];
    float2 h = H2[node * 32 + lane];
    float ax = di * di * h.x, ay = di * di * h.y;

    int beg = g_off[node];
    int end = g_off[node + 1];
    int j = beg;
    for (; j + 4 <= end; j += 4) {
        int s0 = g_csr[j], s1 = g_csr[j + 1], s2 = g_csr[j + 2], s3 = g_csr[j + 3];
        float w0 = di * g_dinv[s0], w1 = di * g_dinv[s1];
        float w2 = di * g_dinv[s2], w3 = di * g_dinv[s3];
        float2 v0 = H2[s0 * 32 + lane];
        float2 v1 = H2[s1 * 32 + lane];
        float2 v2 = H2[s2 * 32 + lane];
        float2 v3 = H2[s3 * 32 + lane];
        ax += w0 * v0.x + w1 * v1.x + w2 * v2.x + w3 * v3.x;
        ay += w0 * v0.y + w1 * v1.y + w2 * v2.y + w3 * v3.y;
    }
    for (; j < end; j++) {
        int s = g_csr[j];
        float w = di * g_dinv[s];
        float2 v = H2[s * 32 + lane];
        ax += w * v.x; ay += w * v.y;
    }

    float2 bb = ((const float2*)bias)[lane];
    ax += bb.x; ay += bb.y;
    if (RELU) { ax = fmaxf(ax, 0.f); ay = fmaxf(ay, 0.f); }
    float2 o = {ax, ay};
    O2[node * 32 + lane] = o;
}

template <bool RELU, int HSEL>
__global__ void agg32_kernel(const float* __restrict__ bias,
                             float* __restrict__ Oarg, int out_sel) {
    const float* H = buf_sel(HSEL);
    float* O = (out_sel < 0) ? Oarg : buf_sel(out_sel);

    int node = (blockIdx.x * blockDim.x + threadIdx.x) >> 5;
    int lane = threadIdx.x & 31;
    if (node >= N_NODES) return;

    float di = g_dinv[node];
    float acc = di * di * H[node * 32 + lane];

    int beg = g_off[node];
    int end = g_off[node + 1];
    int j = beg;
    for (; j + 4 <= end; j += 4) {
        int s0 = g_csr[j], s1 = g_csr[j + 1], s2 = g_csr[j + 2], s3 = g_csr[j + 3];
        float w0 = di * g_dinv[s0], w1 = di * g_dinv[s1];
        float w2 = di * g_dinv[s2], w3 = di * g_dinv[s3];
        acc += w0 * H[s0 * 32 + lane] + w1 * H[s1 * 32 + lane]
             + w2 * H[s2 * 32 + lane] + w3 * H[s3 * 32 + lane];
    }
    for (; j < end; j++) {
        int s = g_csr[j];
        acc += di * g_dinv[s] * H[s * 32 + lane];
    }

    float v = acc + bias[lane];
    if (RELU) v = fmaxf(v, 0.f);
    O[node * 32 + lane] = v;
}

// ---------------------------------------------------------------- launch
extern "C" void kernel_launch(void* const* d_in, const int* in_sizes, int n_in,
                              void* d_out, int out_size) {
    const float* x  = (const float*)d_in[0];
    const int*   ei = (const int*)d_in[1];
    const float* W1 = (const float*)d_in[2];
    const float* b1 = (const float*)d_in[3];
    const float* W2 = (const float*)d_in[4];
    const float* b2 = (const float*)d_in[5];
    float*       out = (float*)d_out;

    // side stream + events for CSR || GEMM1 overlap (created once, reused;
    // stream/event creation is host-side and capture-safe outside captured ops)
    static cudaStream_t s_side = nullptr;
    static cudaEvent_t  s_fork = nullptr, s_join = nullptr;
    if (!s_side) {
        if (cudaStreamCreateWithFlags(&s_side, cudaStreamNonBlocking) != cudaSuccess)
            s_side = nullptr;
        cudaEventCreateWithFlags(&s_fork, cudaEventDisableTiming);
        cudaEventCreateWithFlags(&s_join, cudaEventDisableTiming);
    }
    cudaStream_t sc = s_side ? s_side : 0;   // fallback: everything serial

    // fork: CSR build on side stream
    if (s_side) {
        cudaEventRecord(s_fork, 0);
        cudaStreamWaitEvent(sc, s_fork, 0);
    }
    zero_deg_kernel<<<(N_NODES / 4 + 255) / 256, 256, 0, sc>>>();
    count_kernel<<<(N_EDGES / 4 + 255) / 256, 256, 0, sc>>>(ei);
    scan_reduce_kernel<<<NB_SCAN, 256, 0, sc>>>();
    scan_part_kernel<<<1, 512, 0, sc>>>();
    scan_final_kernel<<<NB_SCAN, 256, 0, sc>>>();
    scatter_kernel<<<(N_EDGES / 2 + 255) / 256, 256, 0, sc>>>(ei);
    if (s_side) {
        cudaEventRecord(s_join, sc);
    }

    // concurrently on main stream: GEMM1  x@W1 -> g_h1
    gemm_kernel<IN_DIM, HID_DIM, 4, 16, -1>
        <<<(N_NODES + 255) / 256, 256>>>(x, W1, 0);

    // join: agg needs both CSR and g_h1
    if (s_side) cudaStreamWaitEvent(0, s_join, 0);

    agg64_kernel<true, 0><<<(N_NODES * 32 + 255) / 256, 256>>>(b1, nullptr, 1);

    gemm_kernel<HID_DIM, OUT_DIM, 4, 16, 1>
        <<<(N_NODES + 511) / 512, 256>>>(nullptr, W2, 2);
    agg32_kernel<false, 2><<<(N_NODES * 32 + 255) / 256, 256>>>(b2, out, -1);
}